// round 15
// baseline (speedup 1.0000x reference)
#include <cuda_runtime.h>
#include <stdint.h>

#define Uc   512
#define Bc   16
#define Dc   512
#define Hc   8
#define Rc   32
#define Sc   16
#define Mc   32
#define HDc  64
#define Qc   560
#define KVc  576
#define PEc  1023
#define BHc  128
#define RUc  544
#define SCALE_F 0.125f
#define NEG_INF_F -100000000.0f

// ---------------- scratch ---------------------------------------------------
__device__ float g_query[Qc * Bc * Dc];
__device__ float g_pos[PEc * Dc];
__device__ float g_bd[(size_t)BHc * Uc * Uc];   // dense rel-shifted bd scores
__device__ float g_attn[Qc * Bc * Dc];

// ---------------- tf32 helpers ---------------------------------------------
__device__ __forceinline__ unsigned f2tf(float x) {
    unsigned r;
    asm("cvt.rna.tf32.f32 %0, %1;" : "=r"(r) : "f"(x));
    return r;
}

__device__ __forceinline__ void mma8(float* c, const unsigned* a, const unsigned* b) {
    asm volatile(
        "mma.sync.aligned.m16n8k8.row.col.f32.tf32.tf32.f32 "
        "{%0,%1,%2,%3},{%4,%5,%6,%7},{%8,%9},{%0,%1,%2,%3};"
        : "+f"(c[0]), "+f"(c[1]), "+f"(c[2]), "+f"(c[3])
        : "r"(a[0]), "r"(a[1]), "r"(a[2]), "r"(a[3]), "r"(b[0]), "r"(b[1]));
}

// ---------------- projection GEMM: C = concat(A0,A1,A2)(M,K) @ W(N,K)^T -----
// MODE is compile-time: 0 plain, 1 kv split, 2 final split+clip.
// launch_bounds(256,3): target ~85 regs for 3 CTA/SM residency.
template<int MODE>
__global__ void __launch_bounds__(256, 3)
proj_mma(const float* __restrict__ A0, const float* __restrict__ A1,
         const float* __restrict__ A2, int t1, int t2,
         const float* __restrict__ W, const float* __restrict__ bias,
         int M, int N, int K,
         float* __restrict__ out1, float* __restrict__ out2) {
    __shared__ unsigned As[128][36];
    __shared__ unsigned Bs[64][36];
    const int t = threadIdx.x;
    const int warp = t >> 5, lane = t & 31;
    const int g = lane >> 2, tig = lane & 3;
    const int wm = warp & 3, wn = warp >> 2;
    const int rowBase = blockIdx.y * 128, colBase = blockIdx.x * 64;

    const int rs  = t >> 3;
    const int c4  = (t & 7) << 2;

    const float* aptr[4];
    bool aval[4];
#pragma unroll
    for (int i = 0; i < 4; i++) {
        int grow = rowBase + rs + 32 * i;
        aval[i] = (grow < M);
        const float* s; int ro;
        if (grow < t1)      { s = A0; ro = grow; }
        else if (grow < t2) { s = A1; ro = grow - t1; }
        else                { s = A2; ro = grow - t2; }
        aptr[i] = s + (size_t)ro * K + c4;
    }
    const float* bptr[2];
#pragma unroll
    for (int i = 0; i < 2; i++)
        bptr[i] = W + (size_t)(colBase + rs + 32 * i) * K + c4;

    float acc[2][4][4];
#pragma unroll
    for (int mi = 0; mi < 2; mi++)
#pragma unroll
        for (int ni = 0; ni < 4; ni++)
#pragma unroll
            for (int j = 0; j < 4; j++) acc[mi][ni][j] = 0.f;

    float4 ar[4], br[2];
#pragma unroll
    for (int i = 0; i < 4; i++)
        ar[i] = aval[i] ? *(const float4*)(aptr[i]) : make_float4(0.f, 0.f, 0.f, 0.f);
#pragma unroll
    for (int i = 0; i < 2; i++)
        br[i] = *(const float4*)(bptr[i]);

    for (int k0 = 0; k0 < K; k0 += 32) {
#pragma unroll
        for (int i = 0; i < 4; i++) {
            int r = rs + 32 * i;
            As[r][c4 + 0] = f2tf(ar[i].x); As[r][c4 + 1] = f2tf(ar[i].y);
            As[r][c4 + 2] = f2tf(ar[i].z); As[r][c4 + 3] = f2tf(ar[i].w);
        }
#pragma unroll
        for (int i = 0; i < 2; i++) {
            int r = rs + 32 * i;
            Bs[r][c4 + 0] = f2tf(br[i].x); Bs[r][c4 + 1] = f2tf(br[i].y);
            Bs[r][c4 + 2] = f2tf(br[i].z); Bs[r][c4 + 3] = f2tf(br[i].w);
        }
        __syncthreads();

        if (k0 + 32 < K) {
#pragma unroll
            for (int i = 0; i < 4; i++)
                ar[i] = aval[i] ? *(const float4*)(aptr[i] + k0 + 32)
                                : make_float4(0.f, 0.f, 0.f, 0.f);
#pragma unroll
            for (int i = 0; i < 2; i++)
                br[i] = *(const float4*)(bptr[i] + k0 + 32);
        }

#pragma unroll
        for (int ks = 0; ks < 4; ks++) {
            unsigned af[2][4], bf[4][2];
#pragma unroll
            for (int mi = 0; mi < 2; mi++) {
                int r0 = wm * 32 + mi * 16 + g;
                int c0 = ks * 8 + tig;
                af[mi][0] = As[r0][c0];
                af[mi][1] = As[r0 + 8][c0];
                af[mi][2] = As[r0][c0 + 4];
                af[mi][3] = As[r0 + 8][c0 + 4];
            }
#pragma unroll
            for (int ni = 0; ni < 4; ni++) {
                int n0 = wn * 32 + ni * 8 + g;
                int kk = ks * 8 + tig;
                bf[ni][0] = Bs[n0][kk];
                bf[ni][1] = Bs[n0][kk + 4];
            }
#pragma unroll
            for (int mi = 0; mi < 2; mi++)
#pragma unroll
                for (int ni = 0; ni < 4; ni++)
                    mma8(acc[mi][ni], af[mi], bf[ni]);
        }
        __syncthreads();
    }

#pragma unroll
    for (int mi = 0; mi < 2; mi++) {
#pragma unroll
        for (int ni = 0; ni < 4; ni++) {
            int col = colBase + wn * 32 + ni * 8 + 2 * tig;
            float b0 = bias ? bias[col] : 0.f;
            float b1 = bias ? bias[col + 1] : 0.f;
#pragma unroll
            for (int half = 0; half < 2; half++) {
                int row = rowBase + wm * 32 + mi * 16 + g + half * 8;
                if (row >= M) continue;
                float v0 = acc[mi][ni][half * 2 + 0] + b0;
                float v1 = acc[mi][ni][half * 2 + 1] + b1;
                if (MODE == 0) {
                    out1[(size_t)row * N + col]     = v0;
                    out1[(size_t)row * N + col + 1] = v1;
                } else if (MODE == 1) {
                    if (col < Dc) {
                        out1[(size_t)row * Dc + col]     = v0;
                        out1[(size_t)row * Dc + col + 1] = v1;
                    } else {
                        out2[(size_t)row * Dc + col - Dc]     = v0;
                        out2[(size_t)row * Dc + col - Dc + 1] = v1;
                    }
                } else {
                    int q = row >> 4;
                    if (q < RUc) {
                        out1[(size_t)row * Dc + col]     = v0;
                        out1[(size_t)row * Dc + col + 1] = v1;
                    } else {
                        v0 = fminf(10.0f, fmaxf(-10.0f, v0));
                        v1 = fminf(10.0f, fmaxf(-10.0f, v1));
                        out2[(size_t)(row - RUc * Bc) * Dc + col]     = v0;
                        out2[(size_t)(row - RUc * Bc) * Dc + col + 1] = v1;
                    }
                }
            }
        }
    }
}

// ---------------- BD dense: g_bd[n][u][jj] = dot(qv_u, pos_{jj+511-u}) ------
// 64x64 tile, 256 threads (8 warps, 2q x 4p), warp tile 32x16.
// Halved per-thread registers -> 3 CTA/SM residency.
__global__ void __launch_bounds__(256, 3)
bd_dense(const float* __restrict__ pbv) {
    __shared__ unsigned As[64][68];
    __shared__ unsigned Bs[64][68];

    const int t = threadIdx.x;
    const int warp = t >> 5, lane = t & 31;
    const int g = lane >> 2, tig = lane & 3;
    const int wm = warp & 1, wn = warp >> 1;        // wm 0..1 (q), wn 0..3 (p)
    const int n = blockIdx.z, b = n >> 3, h = n & 7;
    const int rowBase = blockIdx.y * 64;                      // u0
    const int colBase = 448 - rowBase + blockIdx.x * 64;      // p0 (>= 0)

    // load A tile: 64 u-rows x 64 k (4 float4-iters with 256 threads)
#pragma unroll
    for (int i = 0; i < 4; i++) {
        int idx = t + i * 256;
        int r = idx >> 4, c4 = (idx & 15) << 2;
        int u = rowBase + r;
        float4 v = *(const float4*)(g_query + ((size_t)(Rc + u) * Bc + b) * Dc + h * HDc + c4);
        float4 p = *(const float4*)(pbv + h * HDc + c4);
        v.x += p.x; v.y += p.y; v.z += p.z; v.w += p.w;
        As[r][c4 + 0] = f2tf(v.x); As[r][c4 + 1] = f2tf(v.y);
        As[r][c4 + 2] = f2tf(v.z); As[r][c4 + 3] = f2tf(v.w);
    }
    // load B tile: 64 p-rows x 64 k
#pragma unroll
    for (int i = 0; i < 4; i++) {
        int idx = t + i * 256;
        int r = idx >> 4, c4 = (idx & 15) << 2;
        int pp = colBase + r;
        float4 w = make_float4(0.f, 0.f, 0.f, 0.f);
        if (pp < PEc)
            w = *(const float4*)(g_pos + (size_t)pp * Dc + h * HDc + c4);
        Bs[r][c4 + 0] = f2tf(w.x); Bs[r][c4 + 1] = f2tf(w.y);
        Bs[r][c4 + 2] = f2tf(w.z); Bs[r][c4 + 3] = f2tf(w.w);
    }
    __syncthreads();

    float acc[2][2][4];
#pragma unroll
    for (int mi = 0; mi < 2; mi++)
#pragma unroll
        for (int ni = 0; ni < 2; ni++)
#pragma unroll
            for (int j = 0; j < 4; j++) acc[mi][ni][j] = 0.f;

#pragma unroll
    for (int ks = 0; ks < 8; ks++) {
        unsigned af[2][4], bf[2][2];
#pragma unroll
        for (int mi = 0; mi < 2; mi++) {
            int r0 = wm * 32 + mi * 16 + g;
            int c0 = ks * 8 + tig;
            af[mi][0] = As[r0][c0];     af[mi][1] = As[r0 + 8][c0];
            af[mi][2] = As[r0][c0 + 4]; af[mi][3] = As[r0 + 8][c0 + 4];
        }
#pragma unroll
        for (int ni = 0; ni < 2; ni++) {
            int n0 = wn * 16 + ni * 8 + g;
            int kk = ks * 8 + tig;
            bf[ni][0] = Bs[n0][kk];
            bf[ni][1] = Bs[n0][kk + 4];
        }
#pragma unroll
        for (int mi = 0; mi < 2; mi++)
#pragma unroll
            for (int ni = 0; ni < 2; ni++)
                mma8(acc[mi][ni], af[mi], bf[ni]);
    }

    // scatter epilogue (per-row constant shift)
#pragma unroll
    for (int mi = 0; mi < 2; mi++) {
#pragma unroll
        for (int half = 0; half < 2; half++) {
            int u = rowBase + wm * 32 + mi * 16 + g + half * 8;
#pragma unroll
            for (int ni = 0; ni < 2; ni++) {
#pragma unroll
                for (int jc = 0; jc < 2; jc++) {
                    int p = colBase + wn * 16 + ni * 8 + 2 * tig + jc;
                    if (p >= PEc) continue;
                    int jj = p + u - (Uc - 1);
                    if (jj >= 0 && jj < Uc)
                        g_bd[((size_t)n * Uc + u) * Uc + jj] = acc[mi][ni][half * 2 + jc];
                }
            }
        }
    }
}

// ---------------- fused attention: S = QK^T + bd, softmax, O = P V ----------
// One block per (n, 64-row q-tile). 128 threads, 4 warps (2 q x 2 k/d).
__global__ void __launch_bounds__(128)
fused_attn(const float* __restrict__ keyt,
           const float* __restrict__ valt,
           const float* __restrict__ pbu,
           const unsigned* __restrict__ mask,
           const int* __restrict__ lengths) {
    extern __shared__ unsigned char dynsmem[];
    unsigned (*Qs)[68] = (unsigned (*)[68])(dynsmem);             // 17408B
    unsigned (*Ks)[68] = (unsigned (*)[68])(dynsmem + 17408);     // 17408B
    unsigned (*Vs)[72] = (unsigned (*)[72])(dynsmem + 34816);     // 18432B
    unsigned (*Ps)[68] = (unsigned (*)[68])(dynsmem + 53248);     // 17408B
    float    (*Ms)[68] = (float    (*)[68])(dynsmem + 53248);     // same region
    __shared__ float redm[2][64];
    __shared__ float reds[2][64];

    const int t = threadIdx.x;
    const int warp = t >> 5, lane = t & 31;
    const int g = lane >> 2, tig = lane & 3;
    const int wm = warp & 1, wn = warp >> 1;
    const int qBase = blockIdx.x * 64;
    const int n = blockIdx.y, b = n >> 3, h = n & 7;
    const int cutoff = (Mc + Rc) + lengths[b];

    // load Q tile (+pbu) once
#pragma unroll
    for (int i = 0; i < 8; i++) {
        int idx = t + i * 128;
        int r = idx >> 4, c4 = (idx & 15) << 2;
        int q = qBase + r;
        float4 v = make_float4(0.f, 0.f, 0.f, 0.f);
        if (q < Qc) {
            v = *(const float4*)(g_query + ((size_t)q * Bc + b) * Dc + h * HDc + c4);
            float4 p = *(const float4*)(pbu + h * HDc + c4);
            v.x += p.x; v.y += p.y; v.z += p.z; v.w += p.w;
        }
        Qs[r][c4 + 0] = f2tf(v.x); Qs[r][c4 + 1] = f2tf(v.y);
        Qs[r][c4 + 2] = f2tf(v.z); Qs[r][c4 + 3] = f2tf(v.w);
    }

    float o[2][4][4];
#pragma unroll
    for (int mi = 0; mi < 2; mi++)
#pragma unroll
        for (int ni = 0; ni < 4; ni++)
#pragma unroll
            for (int j = 0; j < 4; j++) o[mi][ni][j] = 0.f;
    float mrun[2][2], lrun[2][2];
#pragma unroll
    for (int mi = 0; mi < 2; mi++)
#pragma unroll
        for (int hf = 0; hf < 2; hf++) { mrun[mi][hf] = -3.0e38f; lrun[mi][hf] = 0.f; }

    for (int kt = 0; kt < KVc / 64; kt++) {
        const int k0 = kt * 64;
        const bool hasbd = (kt >= 1);
        __syncthreads();

        // load K, V tiles (coalesced) and stage mask/bd into Ms
#pragma unroll
        for (int i = 0; i < 8; i++) {
            int idx = t + i * 128;
            int r = idx >> 4, c4 = (idx & 15) << 2;
            size_t goff = ((size_t)(k0 + r) * Bc + b) * Dc + h * HDc + c4;
            float4 kv = *(const float4*)(keyt + goff);
            Ks[r][c4 + 0] = f2tf(kv.x); Ks[r][c4 + 1] = f2tf(kv.y);
            Ks[r][c4 + 2] = f2tf(kv.z); Ks[r][c4 + 3] = f2tf(kv.w);
            float4 vv = *(const float4*)(valt + goff);
            Vs[r][c4 + 0] = f2tf(vv.x); Vs[r][c4 + 1] = f2tf(vv.y);
            Vs[r][c4 + 2] = f2tf(vv.z); Vs[r][c4 + 3] = f2tf(vv.w);

            int q = qBase + r;
            int k = k0 + c4;
            float4 st;
            if (q < Qc) {
                uint4 mk = *(const uint4*)(mask + (size_t)q * KVc + k);
                float4 bd4 = make_float4(0.f, 0.f, 0.f, 0.f);
                if (hasbd && q >= Rc && q < Rc + Uc)
                    bd4 = *(const float4*)(g_bd + ((size_t)n * Uc + (q - Rc)) * Uc + (k - (Mc + Rc)));
                st.x = (mk.x != 0u || k + 0 >= cutoff) ? -1e30f : bd4.x;
                st.y = (mk.y != 0u || k + 1 >= cutoff) ? -1e30f : bd4.y;
                st.z = (mk.z != 0u || k + 2 >= cutoff) ? -1e30f : bd4.z;
                st.w = (mk.w != 0u || k + 3 >= cutoff) ? -1e30f : bd4.w;
            } else {
                st = make_float4(-1e30f, -1e30f, -1e30f, -1e30f);
            }
            *(float4*)&Ms[r][c4] = st;
        }
        __syncthreads();

        // S = Q K^T
        float s[2][4][4];
#pragma unroll
        for (int mi = 0; mi < 2; mi++)
#pragma unroll
            for (int ni = 0; ni < 4; ni++)
#pragma unroll
                for (int j = 0; j < 4; j++) s[mi][ni][j] = 0.f;
#pragma unroll
        for (int ks = 0; ks < 8; ks++) {
            unsigned af[2][4], bf[4][2];
#pragma unroll
            for (int mi = 0; mi < 2; mi++) {
                int r0 = wm * 32 + mi * 16 + g;
                int c0 = ks * 8 + tig;
                af[mi][0] = Qs[r0][c0];     af[mi][1] = Qs[r0 + 8][c0];
                af[mi][2] = Qs[r0][c0 + 4]; af[mi][3] = Qs[r0 + 8][c0 + 4];
            }
#pragma unroll
            for (int ni = 0; ni < 4; ni++) {
                int n0 = wn * 32 + ni * 8 + g;
                int kk = ks * 8 + tig;
                bf[ni][0] = Ks[n0][kk];
                bf[ni][1] = Ks[n0][kk + 4];
            }
#pragma unroll
            for (int mi = 0; mi < 2; mi++)
#pragma unroll
                for (int ni = 0; ni < 4; ni++)
                    mma8(s[mi][ni], af[mi], bf[ni]);
        }

        // epilogue: v = fmax((s + Ms) * SCALE, NEG_INF)
#pragma unroll
        for (int mi = 0; mi < 2; mi++)
#pragma unroll
            for (int j = 0; j < 4; j++) {
                int row = wm * 32 + mi * 16 + (j >> 1) * 8 + g;
#pragma unroll
                for (int ni = 0; ni < 4; ni++) {
                    int col = wn * 32 + ni * 8 + 2 * tig + (j & 1);
                    float v = (s[mi][ni][j] + Ms[row][col]) * SCALE_F;
                    s[mi][ni][j] = fmaxf(v, NEG_INF_F);
                }
            }

        // row max
#pragma unroll
        for (int mi = 0; mi < 2; mi++)
#pragma unroll
            for (int hf = 0; hf < 2; hf++) {
                float x = -3.4e38f;
#pragma unroll
                for (int ni = 0; ni < 4; ni++)
                    x = fmaxf(x, fmaxf(s[mi][ni][2 * hf], s[mi][ni][2 * hf + 1]));
                x = fmaxf(x, __shfl_xor_sync(0xffffffffu, x, 1));
                x = fmaxf(x, __shfl_xor_sync(0xffffffffu, x, 2));
                if (tig == 0) redm[wn][wm * 32 + mi * 16 + hf * 8 + g] = x;
            }
        __syncthreads();

        float mnew[2][2], fac[2][2];
#pragma unroll
        for (int mi = 0; mi < 2; mi++)
#pragma unroll
            for (int hf = 0; hf < 2; hf++) {
                int row = wm * 32 + mi * 16 + hf * 8 + g;
                float mt = fmaxf(redm[0][row], redm[1][row]);
                float mn = fmaxf(mrun[mi][hf], mt);
                fac[mi][hf] = __expf(mrun[mi][hf] - mn);
                mnew[mi][hf] = mn;
            }

        // exp + per-warp row sums
#pragma unroll
        for (int mi = 0; mi < 2; mi++)
#pragma unroll
            for (int hf = 0; hf < 2; hf++) {
                float ssum = 0.f;
#pragma unroll
                for (int ni = 0; ni < 4; ni++) {
#pragma unroll
                    for (int c = 0; c < 2; c++) {
                        float p = __expf(s[mi][ni][2 * hf + c] - mnew[mi][hf]);
                        s[mi][ni][2 * hf + c] = p;
                        ssum += p;
                    }
                }
                ssum += __shfl_xor_sync(0xffffffffu, ssum, 1);
                ssum += __shfl_xor_sync(0xffffffffu, ssum, 2);
                if (tig == 0) reds[wn][wm * 32 + mi * 16 + hf * 8 + g] = ssum;
            }

        // rescale O accumulators
#pragma unroll
        for (int mi = 0; mi < 2; mi++)
#pragma unroll
            for (int ni = 0; ni < 4; ni++)
#pragma unroll
                for (int j = 0; j < 4; j++)
                    o[mi][ni][j] *= fac[mi][j >> 1];

        // write P tile to smem (tf32)
#pragma unroll
        for (int mi = 0; mi < 2; mi++)
#pragma unroll
            for (int j = 0; j < 4; j++) {
                int row = wm * 32 + mi * 16 + (j >> 1) * 8 + g;
#pragma unroll
                for (int ni = 0; ni < 4; ni++) {
                    int col = wn * 32 + ni * 8 + 2 * tig + (j & 1);
                    Ps[row][col] = f2tf(s[mi][ni][j]);
                }
            }
        __syncthreads();

        // update l, m
#pragma unroll
        for (int mi = 0; mi < 2; mi++)
#pragma unroll
            for (int hf = 0; hf < 2; hf++) {
                int row = wm * 32 + mi * 16 + hf * 8 + g;
                lrun[mi][hf] = lrun[mi][hf] * fac[mi][hf] + reds[0][row] + reds[1][row];
                mrun[mi][hf] = mnew[mi][hf];
            }

        // O += P V
#pragma unroll
        for (int ks = 0; ks < 8; ks++) {
            unsigned af[2][4], bf[4][2];
#pragma unroll
            for (int mi = 0; mi < 2; mi++) {
                int r0 = wm * 32 + mi * 16 + g;
                int c0 = ks * 8 + tig;
                af[mi][0] = Ps[r0][c0];     af[mi][1] = Ps[r0 + 8][c0];
                af[mi][2] = Ps[r0][c0 + 4]; af[mi][3] = Ps[r0 + 8][c0 + 4];
            }
#pragma unroll
            for (int ni = 0; ni < 4; ni++) {
                int col = wn * 32 + ni * 8 + g;
                int kk = ks * 8 + tig;
                bf[ni][0] = Vs[kk][col];
                bf[ni][1] = Vs[kk + 4][col];
            }
#pragma unroll
            for (int mi = 0; mi < 2; mi++)
#pragma unroll
                for (int ni = 0; ni < 4; ni++)
                    mma8(o[mi][ni], af[mi], bf[ni]);
        }
    }

    // final: O / l -> g_attn
#pragma unroll
    for (int mi = 0; mi < 2; mi++)
#pragma unroll
        for (int j = 0; j < 4; j++) {
            int row = wm * 32 + mi * 16 + (j >> 1) * 8 + g;
            int q = qBase + row;
            if (q >= Qc) continue;
            float inv = 1.0f / lrun[mi][j >> 1];
#pragma unroll
            for (int ni = 0; ni < 4; ni++) {
                int d = wn * 32 + ni * 8 + 2 * tig + (j & 1);
                g_attn[((size_t)q * Bc + b) * Dc + h * HDc + d] = o[mi][ni][j] * inv;
            }
        }
}

// ---------------- launch ----------------------------------------------------
extern "C" void kernel_launch(void* const* d_in, const int* in_sizes, int n_in,
                              void* d_out, int out_size) {
    const float*    utterance     = (const float*)d_in[0];
    const int*      lengths       = (const int*)d_in[1];
    const float*    right_context = (const float*)d_in[2];
    const float*    summary       = (const float*)d_in[3];
    const float*    memory        = (const float*)d_in[4];
    const unsigned* attn_mask     = (const unsigned*)d_in[5];
    const float*    pos_emb       = (const float*)d_in[6];
    const float*    Wq            = (const float*)d_in[7];
    const float*    bq            = (const float*)d_in[8];
    const float*    Wkv           = (const float*)d_in[9];
    const float*    bkv           = (const float*)d_in[10];
    const float*    Wo            = (const float*)d_in[11];
    const float*    bo            = (const float*)d_in[12];
    const float*    Wpos          = (const float*)d_in[13];
    const float*    pbu           = (const float*)d_in[14];
    const float*    pbv           = (const float*)d_in[15];

    float* out      = (float*)d_out;
    float* out_rcu  = out;                                    // (R+U, B, D)
    float* out_mem  = out + (size_t)RUc * Bc * Dc;            // (S, B, D)
    float* out_key  = out + (size_t)Qc * Bc * Dc;             // (KV, B, D)
    float* out_val  = out_key + (size_t)KVc * Bc * Dc;        // (KV, B, D)

    void *p_query_, *p_pos_, *p_attn_;
    cudaGetSymbolAddress(&p_query_, g_query);
    cudaGetSymbolAddress(&p_pos_,  g_pos);
    cudaGetSymbolAddress(&p_attn_, g_attn);
    float* p_query = (float*)p_query_;
    float* p_pos   = (float*)p_pos_;
    float* p_attn  = (float*)p_attn_;

    const int FUSED_SMEM = 70656;
    cudaFuncSetAttribute(fused_attn, cudaFuncAttributeMaxDynamicSharedMemorySize, FUSED_SMEM);

    // 1) projections (tf32 MMA), mode compile-time specialized
    proj_mma<0><<<dim3(Dc / 64, (Qc * Bc) / 128), 256>>>(
        right_context, utterance, summary, Rc * Bc, RUc * Bc,
        Wq, bq, Qc * Bc, Dc, Dc, p_query, nullptr);
    proj_mma<1><<<dim3((2 * Dc) / 64, (KVc * Bc) / 128), 256>>>(
        memory, right_context, utterance, Mc * Bc, (Mc + Rc) * Bc,
        Wkv, bkv, KVc * Bc, 2 * Dc, Dc, out_key, out_val);
    proj_mma<0><<<dim3(Dc / 64, (PEc + 127) / 128), 256>>>(
        pos_emb, pos_emb, pos_emb, PEc, PEc,
        Wpos, nullptr, PEc, Dc, Dc, p_pos, nullptr);

    // 2) dense rel-shifted bd scores (256 threads, 64x64 tile, 3 CTA/SM)
    bd_dense<<<dim3(9, Uc / 64, BHc), 256>>>(pbv);

    // 3) fused attention (AC scores + bd + masks + softmax + PV)
    fused_attn<<<dim3((Qc + 63) / 64, BHc), 128, FUSED_SMEM>>>(out_key, out_val, pbu, attn_mask, lengths);

    // 4) output projection with split + clip
    proj_mma<2><<<dim3(Dc / 64, (Qc * Bc) / 128), 256>>>(
        p_attn, p_attn, p_attn, Qc * Bc, Qc * Bc,
        Wo, bo, Qc * Bc, Dc, Dc, out_rcu, out_mem);
}

// round 16
// speedup vs baseline: 1.0466x; 1.0466x over previous
#include <cuda_runtime.h>
#include <stdint.h>

#define Uc   512
#define Bc   16
#define Dc   512
#define Hc   8
#define Rc   32
#define Sc   16
#define Mc   32
#define HDc  64
#define Qc   560
#define KVc  576
#define PEc  1023
#define BHc  128
#define RUc  544
#define SCALE_F 0.125f
#define NEG_INF_F -100000000.0f

// ---------------- scratch ---------------------------------------------------
__device__ float g_query[Qc * Bc * Dc];
__device__ float g_pos[PEc * Dc];
__device__ float g_bd[(size_t)BHc * Uc * Uc];   // dense rel-shifted bd scores
__device__ float g_attn[Qc * Bc * Dc];

// ---------------- tf32 helpers ---------------------------------------------
__device__ __forceinline__ unsigned f2tf(float x) {
    unsigned r;
    asm("cvt.rna.tf32.f32 %0, %1;" : "=r"(r) : "f"(x));
    return r;
}

__device__ __forceinline__ void mma8(float* c, const unsigned* a, const unsigned* b) {
    asm volatile(
        "mma.sync.aligned.m16n8k8.row.col.f32.tf32.tf32.f32 "
        "{%0,%1,%2,%3},{%4,%5,%6,%7},{%8,%9},{%0,%1,%2,%3};"
        : "+f"(c[0]), "+f"(c[1]), "+f"(c[2]), "+f"(c[3])
        : "r"(a[0]), "r"(a[1]), "r"(a[2]), "r"(a[3]), "r"(b[0]), "r"(b[1]));
}

// ---------------- projection GEMM: C = concat(A0,A1,A2)(M,K) @ W(N,K)^T -----
// MODE compile-time: 0 plain, 1 kv split, 2 final split+clip.
template<int MODE>
__global__ void __launch_bounds__(256, 2)
proj_mma(const float* __restrict__ A0, const float* __restrict__ A1,
         const float* __restrict__ A2, int t1, int t2,
         const float* __restrict__ W, const float* __restrict__ bias,
         int M, int N, int K,
         float* __restrict__ out1, float* __restrict__ out2) {
    __shared__ unsigned As[128][36];
    __shared__ unsigned Bs[64][36];
    const int t = threadIdx.x;
    const int warp = t >> 5, lane = t & 31;
    const int g = lane >> 2, tig = lane & 3;
    const int wm = warp & 3, wn = warp >> 2;
    const int rowBase = blockIdx.y * 128, colBase = blockIdx.x * 64;

    const int rs  = t >> 3;
    const int c4  = (t & 7) << 2;

    const float* aptr[4];
    bool aval[4];
#pragma unroll
    for (int i = 0; i < 4; i++) {
        int grow = rowBase + rs + 32 * i;
        aval[i] = (grow < M);
        const float* s; int ro;
        if (grow < t1)      { s = A0; ro = grow; }
        else if (grow < t2) { s = A1; ro = grow - t1; }
        else                { s = A2; ro = grow - t2; }
        aptr[i] = s + (size_t)ro * K + c4;
    }
    const float* bptr[2];
#pragma unroll
    for (int i = 0; i < 2; i++)
        bptr[i] = W + (size_t)(colBase + rs + 32 * i) * K + c4;

    float acc[2][4][4];
#pragma unroll
    for (int mi = 0; mi < 2; mi++)
#pragma unroll
        for (int ni = 0; ni < 4; ni++)
#pragma unroll
            for (int j = 0; j < 4; j++) acc[mi][ni][j] = 0.f;

    float4 ar[4], br[2];
#pragma unroll
    for (int i = 0; i < 4; i++)
        ar[i] = aval[i] ? *(const float4*)(aptr[i]) : make_float4(0.f, 0.f, 0.f, 0.f);
#pragma unroll
    for (int i = 0; i < 2; i++)
        br[i] = *(const float4*)(bptr[i]);

    for (int k0 = 0; k0 < K; k0 += 32) {
#pragma unroll
        for (int i = 0; i < 4; i++) {
            int r = rs + 32 * i;
            As[r][c4 + 0] = f2tf(ar[i].x); As[r][c4 + 1] = f2tf(ar[i].y);
            As[r][c4 + 2] = f2tf(ar[i].z); As[r][c4 + 3] = f2tf(ar[i].w);
        }
#pragma unroll
        for (int i = 0; i < 2; i++) {
            int r = rs + 32 * i;
            Bs[r][c4 + 0] = f2tf(br[i].x); Bs[r][c4 + 1] = f2tf(br[i].y);
            Bs[r][c4 + 2] = f2tf(br[i].z); Bs[r][c4 + 3] = f2tf(br[i].w);
        }
        __syncthreads();

        if (k0 + 32 < K) {
#pragma unroll
            for (int i = 0; i < 4; i++)
                ar[i] = aval[i] ? *(const float4*)(aptr[i] + k0 + 32)
                                : make_float4(0.f, 0.f, 0.f, 0.f);
#pragma unroll
            for (int i = 0; i < 2; i++)
                br[i] = *(const float4*)(bptr[i] + k0 + 32);
        }

#pragma unroll
        for (int ks = 0; ks < 4; ks++) {
            unsigned af[2][4], bf[4][2];
#pragma unroll
            for (int mi = 0; mi < 2; mi++) {
                int r0 = wm * 32 + mi * 16 + g;
                int c0 = ks * 8 + tig;
                af[mi][0] = As[r0][c0];
                af[mi][1] = As[r0 + 8][c0];
                af[mi][2] = As[r0][c0 + 4];
                af[mi][3] = As[r0 + 8][c0 + 4];
            }
#pragma unroll
            for (int ni = 0; ni < 4; ni++) {
                int n0 = wn * 32 + ni * 8 + g;
                int kk = ks * 8 + tig;
                bf[ni][0] = Bs[n0][kk];
                bf[ni][1] = Bs[n0][kk + 4];
            }
#pragma unroll
            for (int mi = 0; mi < 2; mi++)
#pragma unroll
                for (int ni = 0; ni < 4; ni++)
                    mma8(acc[mi][ni], af[mi], bf[ni]);
        }
        __syncthreads();
    }

#pragma unroll
    for (int mi = 0; mi < 2; mi++) {
#pragma unroll
        for (int ni = 0; ni < 4; ni++) {
            int col = colBase + wn * 32 + ni * 8 + 2 * tig;
            float b0 = bias ? bias[col] : 0.f;
            float b1 = bias ? bias[col + 1] : 0.f;
#pragma unroll
            for (int half = 0; half < 2; half++) {
                int row = rowBase + wm * 32 + mi * 16 + g + half * 8;
                if (row >= M) continue;
                float v0 = acc[mi][ni][half * 2 + 0] + b0;
                float v1 = acc[mi][ni][half * 2 + 1] + b1;
                if (MODE == 0) {
                    out1[(size_t)row * N + col]     = v0;
                    out1[(size_t)row * N + col + 1] = v1;
                } else if (MODE == 1) {
                    if (col < Dc) {
                        out1[(size_t)row * Dc + col]     = v0;
                        out1[(size_t)row * Dc + col + 1] = v1;
                    } else {
                        out2[(size_t)row * Dc + col - Dc]     = v0;
                        out2[(size_t)row * Dc + col - Dc + 1] = v1;
                    }
                } else {
                    int q = row >> 4;
                    if (q < RUc) {
                        out1[(size_t)row * Dc + col]     = v0;
                        out1[(size_t)row * Dc + col + 1] = v1;
                    } else {
                        v0 = fminf(10.0f, fmaxf(-10.0f, v0));
                        v1 = fminf(10.0f, fmaxf(-10.0f, v1));
                        out2[(size_t)(row - RUc * Bc) * Dc + col]     = v0;
                        out2[(size_t)(row - RUc * Bc) * Dc + col + 1] = v1;
                    }
                }
            }
        }
    }
}

// ---------------- BD dense: 64x64 tile, 256 threads (2q x 4p warps) ---------
__global__ void __launch_bounds__(256, 3)
bd_dense(const float* __restrict__ pbv) {
    __shared__ unsigned As[64][68];
    __shared__ unsigned Bs[64][68];

    const int t = threadIdx.x;
    const int warp = t >> 5, lane = t & 31;
    const int g = lane >> 2, tig = lane & 3;
    const int wm = warp & 1, wn = warp >> 1;
    const int n = blockIdx.z, b = n >> 3, h = n & 7;
    const int rowBase = blockIdx.y * 64;                      // u0
    const int colBase = 448 - rowBase + blockIdx.x * 64;      // p0 (>= 0)

#pragma unroll
    for (int i = 0; i < 4; i++) {
        int idx = t + i * 256;
        int r = idx >> 4, c4 = (idx & 15) << 2;
        int u = rowBase + r;
        float4 v = *(const float4*)(g_query + ((size_t)(Rc + u) * Bc + b) * Dc + h * HDc + c4);
        float4 p = *(const float4*)(pbv + h * HDc + c4);
        v.x += p.x; v.y += p.y; v.z += p.z; v.w += p.w;
        As[r][c4 + 0] = f2tf(v.x); As[r][c4 + 1] = f2tf(v.y);
        As[r][c4 + 2] = f2tf(v.z); As[r][c4 + 3] = f2tf(v.w);
    }
#pragma unroll
    for (int i = 0; i < 4; i++) {
        int idx = t + i * 256;
        int r = idx >> 4, c4 = (idx & 15) << 2;
        int pp = colBase + r;
        float4 w = make_float4(0.f, 0.f, 0.f, 0.f);
        if (pp < PEc)
            w = *(const float4*)(g_pos + (size_t)pp * Dc + h * HDc + c4);
        Bs[r][c4 + 0] = f2tf(w.x); Bs[r][c4 + 1] = f2tf(w.y);
        Bs[r][c4 + 2] = f2tf(w.z); Bs[r][c4 + 3] = f2tf(w.w);
    }
    __syncthreads();

    float acc[2][2][4];
#pragma unroll
    for (int mi = 0; mi < 2; mi++)
#pragma unroll
        for (int ni = 0; ni < 2; ni++)
#pragma unroll
            for (int j = 0; j < 4; j++) acc[mi][ni][j] = 0.f;

#pragma unroll
    for (int ks = 0; ks < 8; ks++) {
        unsigned af[2][4], bf[2][2];
#pragma unroll
        for (int mi = 0; mi < 2; mi++) {
            int r0 = wm * 32 + mi * 16 + g;
            int c0 = ks * 8 + tig;
            af[mi][0] = As[r0][c0];     af[mi][1] = As[r0 + 8][c0];
            af[mi][2] = As[r0][c0 + 4]; af[mi][3] = As[r0 + 8][c0 + 4];
        }
#pragma unroll
        for (int ni = 0; ni < 2; ni++) {
            int n0 = wn * 16 + ni * 8 + g;
            int kk = ks * 8 + tig;
            bf[ni][0] = Bs[n0][kk];
            bf[ni][1] = Bs[n0][kk + 4];
        }
#pragma unroll
        for (int mi = 0; mi < 2; mi++)
#pragma unroll
            for (int ni = 0; ni < 2; ni++)
                mma8(acc[mi][ni], af[mi], bf[ni]);
    }

#pragma unroll
    for (int mi = 0; mi < 2; mi++) {
#pragma unroll
        for (int half = 0; half < 2; half++) {
            int u = rowBase + wm * 32 + mi * 16 + g + half * 8;
#pragma unroll
            for (int ni = 0; ni < 2; ni++) {
#pragma unroll
                for (int jc = 0; jc < 2; jc++) {
                    int p = colBase + wn * 16 + ni * 8 + 2 * tig + jc;
                    if (p >= PEc) continue;
                    int jj = p + u - (Uc - 1);
                    if (jj >= 0 && jj < Uc)
                        g_bd[((size_t)n * Uc + u) * Uc + jj] = acc[mi][ni][half * 2 + jc];
                }
            }
        }
    }
}

// ---------------- fused attention: S = QK^T + bd, softmax, O = P V ----------
__global__ void __launch_bounds__(128)
fused_attn(const float* __restrict__ keyt,
           const float* __restrict__ valt,
           const float* __restrict__ pbu,
           const unsigned* __restrict__ mask,
           const int* __restrict__ lengths) {
    extern __shared__ unsigned char dynsmem[];
    unsigned (*Qs)[68] = (unsigned (*)[68])(dynsmem);             // 17408B
    unsigned (*Ks)[68] = (unsigned (*)[68])(dynsmem + 17408);     // 17408B
    unsigned (*Vs)[72] = (unsigned (*)[72])(dynsmem + 34816);     // 18432B
    unsigned (*Ps)[68] = (unsigned (*)[68])(dynsmem + 53248);     // 17408B
    float    (*Ms)[68] = (float    (*)[68])(dynsmem + 53248);     // same region
    __shared__ float redm[2][64];
    __shared__ float reds[2][64];

    const int t = threadIdx.x;
    const int warp = t >> 5, lane = t & 31;
    const int g = lane >> 2, tig = lane & 3;
    const int wm = warp & 1, wn = warp >> 1;
    const int qBase = blockIdx.x * 64;
    const int n = blockIdx.y, b = n >> 3, h = n & 7;
    const int cutoff = (Mc + Rc) + lengths[b];

#pragma unroll
    for (int i = 0; i < 8; i++) {
        int idx = t + i * 128;
        int r = idx >> 4, c4 = (idx & 15) << 2;
        int q = qBase + r;
        float4 v = make_float4(0.f, 0.f, 0.f, 0.f);
        if (q < Qc) {
            v = *(const float4*)(g_query + ((size_t)q * Bc + b) * Dc + h * HDc + c4);
            float4 p = *(const float4*)(pbu + h * HDc + c4);
            v.x += p.x; v.y += p.y; v.z += p.z; v.w += p.w;
        }
        Qs[r][c4 + 0] = f2tf(v.x); Qs[r][c4 + 1] = f2tf(v.y);
        Qs[r][c4 + 2] = f2tf(v.z); Qs[r][c4 + 3] = f2tf(v.w);
    }

    float o[2][4][4];
#pragma unroll
    for (int mi = 0; mi < 2; mi++)
#pragma unroll
        for (int ni = 0; ni < 4; ni++)
#pragma unroll
            for (int j = 0; j < 4; j++) o[mi][ni][j] = 0.f;
    float mrun[2][2], lrun[2][2];
#pragma unroll
    for (int mi = 0; mi < 2; mi++)
#pragma unroll
        for (int hf = 0; hf < 2; hf++) { mrun[mi][hf] = -3.0e38f; lrun[mi][hf] = 0.f; }

    for (int kt = 0; kt < KVc / 64; kt++) {
        const int k0 = kt * 64;
        const bool hasbd = (kt >= 1);
        __syncthreads();

#pragma unroll
        for (int i = 0; i < 8; i++) {
            int idx = t + i * 128;
            int r = idx >> 4, c4 = (idx & 15) << 2;
            size_t goff = ((size_t)(k0 + r) * Bc + b) * Dc + h * HDc + c4;
            float4 kv = *(const float4*)(keyt + goff);
            Ks[r][c4 + 0] = f2tf(kv.x); Ks[r][c4 + 1] = f2tf(kv.y);
            Ks[r][c4 + 2] = f2tf(kv.z); Ks[r][c4 + 3] = f2tf(kv.w);
            float4 vv = *(const float4*)(valt + goff);
            Vs[r][c4 + 0] = f2tf(vv.x); Vs[r][c4 + 1] = f2tf(vv.y);
            Vs[r][c4 + 2] = f2tf(vv.z); Vs[r][c4 + 3] = f2tf(vv.w);

            int q = qBase + r;
            int k = k0 + c4;
            float4 st;
            if (q < Qc) {
                uint4 mk = *(const uint4*)(mask + (size_t)q * KVc + k);
                float4 bd4 = make_float4(0.f, 0.f, 0.f, 0.f);
                if (hasbd && q >= Rc && q < Rc + Uc)
                    bd4 = *(const float4*)(g_bd + ((size_t)n * Uc + (q - Rc)) * Uc + (k - (Mc + Rc)));
                st.x = (mk.x != 0u || k + 0 >= cutoff) ? -1e30f : bd4.x;
                st.y = (mk.y != 0u || k + 1 >= cutoff) ? -1e30f : bd4.y;
                st.z = (mk.z != 0u || k + 2 >= cutoff) ? -1e30f : bd4.z;
                st.w = (mk.w != 0u || k + 3 >= cutoff) ? -1e30f : bd4.w;
            } else {
                st = make_float4(-1e30f, -1e30f, -1e30f, -1e30f);
            }
            *(float4*)&Ms[r][c4] = st;
        }
        __syncthreads();

        float s[2][4][4];
#pragma unroll
        for (int mi = 0; mi < 2; mi++)
#pragma unroll
            for (int ni = 0; ni < 4; ni++)
#pragma unroll
                for (int j = 0; j < 4; j++) s[mi][ni][j] = 0.f;
#pragma unroll
        for (int ks = 0; ks < 8; ks++) {
            unsigned af[2][4], bf[4][2];
#pragma unroll
            for (int mi = 0; mi < 2; mi++) {
                int r0 = wm * 32 + mi * 16 + g;
                int c0 = ks * 8 + tig;
                af[mi][0] = Qs[r0][c0];     af[mi][1] = Qs[r0 + 8][c0];
                af[mi][2] = Qs[r0][c0 + 4]; af[mi][3] = Qs[r0 + 8][c0 + 4];
            }
#pragma unroll
            for (int ni = 0; ni < 4; ni++) {
                int n0 = wn * 32 + ni * 8 + g;
                int kk = ks * 8 + tig;
                bf[ni][0] = Ks[n0][kk];
                bf[ni][1] = Ks[n0][kk + 4];
            }
#pragma unroll
            for (int mi = 0; mi < 2; mi++)
#pragma unroll
                for (int ni = 0; ni < 4; ni++)
                    mma8(s[mi][ni], af[mi], bf[ni]);
        }

#pragma unroll
        for (int mi = 0; mi < 2; mi++)
#pragma unroll
            for (int j = 0; j < 4; j++) {
                int row = wm * 32 + mi * 16 + (j >> 1) * 8 + g;
#pragma unroll
                for (int ni = 0; ni < 4; ni++) {
                    int col = wn * 32 + ni * 8 + 2 * tig + (j & 1);
                    float v = (s[mi][ni][j] + Ms[row][col]) * SCALE_F;
                    s[mi][ni][j] = fmaxf(v, NEG_INF_F);
                }
            }

#pragma unroll
        for (int mi = 0; mi < 2; mi++)
#pragma unroll
            for (int hf = 0; hf < 2; hf++) {
                float x = -3.4e38f;
#pragma unroll
                for (int ni = 0; ni < 4; ni++)
                    x = fmaxf(x, fmaxf(s[mi][ni][2 * hf], s[mi][ni][2 * hf + 1]));
                x = fmaxf(x, __shfl_xor_sync(0xffffffffu, x, 1));
                x = fmaxf(x, __shfl_xor_sync(0xffffffffu, x, 2));
                if (tig == 0) redm[wn][wm * 32 + mi * 16 + hf * 8 + g] = x;
            }
        __syncthreads();

        float mnew[2][2], fac[2][2];
#pragma unroll
        for (int mi = 0; mi < 2; mi++)
#pragma unroll
            for (int hf = 0; hf < 2; hf++) {
                int row = wm * 32 + mi * 16 + hf * 8 + g;
                float mt = fmaxf(redm[0][row], redm[1][row]);
                float mn = fmaxf(mrun[mi][hf], mt);
                fac[mi][hf] = __expf(mrun[mi][hf] - mn);
                mnew[mi][hf] = mn;
            }

#pragma unroll
        for (int mi = 0; mi < 2; mi++)
#pragma unroll
            for (int hf = 0; hf < 2; hf++) {
                float ssum = 0.f;
#pragma unroll
                for (int ni = 0; ni < 4; ni++) {
#pragma unroll
                    for (int c = 0; c < 2; c++) {
                        float p = __expf(s[mi][ni][2 * hf + c] - mnew[mi][hf]);
                        s[mi][ni][2 * hf + c] = p;
                        ssum += p;
                    }
                }
                ssum += __shfl_xor_sync(0xffffffffu, ssum, 1);
                ssum += __shfl_xor_sync(0xffffffffu, ssum, 2);
                if (tig == 0) reds[wn][wm * 32 + mi * 16 + hf * 8 + g] = ssum;
            }

#pragma unroll
        for (int mi = 0; mi < 2; mi++)
#pragma unroll
            for (int ni = 0; ni < 4; ni++)
#pragma unroll
                for (int j = 0; j < 4; j++)
                    o[mi][ni][j] *= fac[mi][j >> 1];

#pragma unroll
        for (int mi = 0; mi < 2; mi++)
#pragma unroll
            for (int j = 0; j < 4; j++) {
                int row = wm * 32 + mi * 16 + (j >> 1) * 8 + g;
#pragma unroll
                for (int ni = 0; ni < 4; ni++) {
                    int col = wn * 32 + ni * 8 + 2 * tig + (j & 1);
                    Ps[row][col] = f2tf(s[mi][ni][j]);
                }
            }
        __syncthreads();

#pragma unroll
        for (int mi = 0; mi < 2; mi++)
#pragma unroll
            for (int hf = 0; hf < 2; hf++) {
                int row = wm * 32 + mi * 16 + hf * 8 + g;
                lrun[mi][hf] = lrun[mi][hf] * fac[mi][hf] + reds[0][row] + reds[1][row];
                mrun[mi][hf] = mnew[mi][hf];
            }

#pragma unroll
        for (int ks = 0; ks < 8; ks++) {
            unsigned af[2][4], bf[4][2];
#pragma unroll
            for (int mi = 0; mi < 2; mi++) {
                int r0 = wm * 32 + mi * 16 + g;
                int c0 = ks * 8 + tig;
                af[mi][0] = Ps[r0][c0];     af[mi][1] = Ps[r0 + 8][c0];
                af[mi][2] = Ps[r0][c0 + 4]; af[mi][3] = Ps[r0 + 8][c0 + 4];
            }
#pragma unroll
            for (int ni = 0; ni < 4; ni++) {
                int col = wn * 32 + ni * 8 + g;
                int kk = ks * 8 + tig;
                bf[ni][0] = Vs[kk][col];
                bf[ni][1] = Vs[kk + 4][col];
            }
#pragma unroll
            for (int mi = 0; mi < 2; mi++)
#pragma unroll
                for (int ni = 0; ni < 4; ni++)
                    mma8(o[mi][ni], af[mi], bf[ni]);
        }
    }

#pragma unroll
    for (int mi = 0; mi < 2; mi++)
#pragma unroll
        for (int j = 0; j < 4; j++) {
            int row = wm * 32 + mi * 16 + (j >> 1) * 8 + g;
            int q = qBase + row;
            if (q >= Qc) continue;
            float inv = 1.0f / lrun[mi][j >> 1];
#pragma unroll
            for (int ni = 0; ni < 4; ni++) {
                int d = wn * 32 + ni * 8 + 2 * tig + (j & 1);
                g_attn[((size_t)q * Bc + b) * Dc + h * HDc + d] = o[mi][ni][j] * inv;
            }
        }
}

// ---------------- launch (fork-join concurrency on static streams) ----------
extern "C" void kernel_launch(void* const* d_in, const int* in_sizes, int n_in,
                              void* d_out, int out_size) {
    const float*    utterance     = (const float*)d_in[0];
    const int*      lengths       = (const int*)d_in[1];
    const float*    right_context = (const float*)d_in[2];
    const float*    summary       = (const float*)d_in[3];
    const float*    memory        = (const float*)d_in[4];
    const unsigned* attn_mask     = (const unsigned*)d_in[5];
    const float*    pos_emb       = (const float*)d_in[6];
    const float*    Wq            = (const float*)d_in[7];
    const float*    bq            = (const float*)d_in[8];
    const float*    Wkv           = (const float*)d_in[9];
    const float*    bkv           = (const float*)d_in[10];
    const float*    Wo            = (const float*)d_in[11];
    const float*    bo            = (const float*)d_in[12];
    const float*    Wpos          = (const float*)d_in[13];
    const float*    pbu           = (const float*)d_in[14];
    const float*    pbv           = (const float*)d_in[15];

    float* out      = (float*)d_out;
    float* out_rcu  = out;                                    // (R+U, B, D)
    float* out_mem  = out + (size_t)RUc * Bc * Dc;            // (S, B, D)
    float* out_key  = out + (size_t)Qc * Bc * Dc;             // (KV, B, D)
    float* out_val  = out_key + (size_t)KVc * Bc * Dc;        // (KV, B, D)

    void *p_query_, *p_pos_, *p_attn_;
    cudaGetSymbolAddress(&p_query_, g_query);
    cudaGetSymbolAddress(&p_pos_,  g_pos);
    cudaGetSymbolAddress(&p_attn_, g_attn);
    float* p_query = (float*)p_query_;
    float* p_pos   = (float*)p_pos_;
    float* p_attn  = (float*)p_attn_;

    const int FUSED_SMEM = 70656;
    cudaFuncSetAttribute(fused_attn, cudaFuncAttributeMaxDynamicSharedMemorySize, FUSED_SMEM);

    // one-time stream/event setup (first call is the uncaptured correctness run)
    static cudaStream_t sA = nullptr, sB = nullptr;
    static cudaEvent_t  evRoot = nullptr, evKV = nullptr, evPos = nullptr;
    if (sA == nullptr) {
        cudaStreamCreateWithFlags(&sA, cudaStreamNonBlocking);
        cudaStreamCreateWithFlags(&sB, cudaStreamNonBlocking);
        cudaEventCreateWithFlags(&evRoot, cudaEventDisableTiming);
        cudaEventCreateWithFlags(&evKV,  cudaEventDisableTiming);
        cudaEventCreateWithFlags(&evPos, cudaEventDisableTiming);
    }

    // fork: kv on sA, pos on sB, q on main stream — all independent
    cudaEventRecord(evRoot, 0);
    cudaStreamWaitEvent(sA, evRoot, 0);
    cudaStreamWaitEvent(sB, evRoot, 0);

    proj_mma<1><<<dim3((2 * Dc) / 64, (KVc * Bc) / 128), 256, 0, sA>>>(
        memory, right_context, utterance, Mc * Bc, (Mc + Rc) * Bc,
        Wkv, bkv, KVc * Bc, 2 * Dc, Dc, out_key, out_val);
    cudaEventRecord(evKV, sA);

    proj_mma<0><<<dim3(Dc / 64, (PEc + 127) / 128), 256, 0, sB>>>(
        pos_emb, pos_emb, pos_emb, PEc, PEc,
        Wpos, nullptr, PEc, Dc, Dc, p_pos, nullptr);
    cudaEventRecord(evPos, sB);

    proj_mma<0><<<dim3(Dc / 64, (Qc * Bc) / 128), 256>>>(
        right_context, utterance, summary, Rc * Bc, RUc * Bc,
        Wq, bq, Qc * Bc, Dc, Dc, p_query, nullptr);

    // bd needs q (in-order on main) + pos
    cudaStreamWaitEvent(0, evPos, 0);
    bd_dense<<<dim3(9, Uc / 64, BHc), 256>>>(pbv);

    // fused needs bd (in-order) + kv
    cudaStreamWaitEvent(0, evKV, 0);
    fused_attn<<<dim3((Qc + 63) / 64, BHc), 128, FUSED_SMEM>>>(out_key, out_val, pbu, attn_mask, lengths);

    // out-proj needs fused (in-order)
    proj_mma<2><<<dim3(Dc / 64, (Qc * Bc) / 128), 256>>>(
        p_attn, p_attn, p_attn, Qc * Bc, Qc * Bc,
        Wo, bo, Qc * Bc, Dc, Dc, out_rcu, out_mem);
}

// round 17
// speedup vs baseline: 1.1396x; 1.0889x over previous
#include <cuda_runtime.h>
#include <stdint.h>

#define Uc   512
#define Bc   16
#define Dc   512
#define Hc   8
#define Rc   32
#define Sc   16
#define Mc   32
#define HDc  64
#define Qc   560
#define KVc  576
#define PEc  1023
#define BHc  128
#define RUc  544
#define SCALE_F 0.125f
#define NEG_INF_F -100000000.0f

// ---------------- scratch ---------------------------------------------------
__device__ float g_query[Qc * Bc * Dc];
__device__ float g_pos[PEc * Dc];
__device__ float g_bd[(size_t)BHc * Uc * Uc];   // dense rel-shifted bd scores
__device__ float g_attn[Qc * Bc * Dc];

// ---------------- tf32 helpers ---------------------------------------------
__device__ __forceinline__ unsigned f2tf(float x) {
    unsigned r;
    asm("cvt.rna.tf32.f32 %0, %1;" : "=r"(r) : "f"(x));
    return r;
}

__device__ __forceinline__ void mma8(float* c, const unsigned* a, const unsigned* b) {
    asm volatile(
        "mma.sync.aligned.m16n8k8.row.col.f32.tf32.tf32.f32 "
        "{%0,%1,%2,%3},{%4,%5,%6,%7},{%8,%9},{%0,%1,%2,%3};"
        : "+f"(c[0]), "+f"(c[1]), "+f"(c[2]), "+f"(c[3])
        : "r"(a[0]), "r"(a[1]), "r"(a[2]), "r"(a[3]), "r"(b[0]), "r"(b[1]));
}

// ---------------- projection GEMM: C = concat(A0,A1,A2)(M,K) @ W(N,K)^T -----
// MODE compile-time: 0 plain, 1 kv split, 2 final split+clip.
template<int MODE>
__global__ void __launch_bounds__(256, 2)
proj_mma(const float* __restrict__ A0, const float* __restrict__ A1,
         const float* __restrict__ A2, int t1, int t2,
         const float* __restrict__ W, const float* __restrict__ bias,
         int M, int N, int K,
         float* __restrict__ out1, float* __restrict__ out2) {
    __shared__ unsigned As[128][36];
    __shared__ unsigned Bs[64][36];
    const int t = threadIdx.x;
    const int warp = t >> 5, lane = t & 31;
    const int g = lane >> 2, tig = lane & 3;
    const int wm = warp & 3, wn = warp >> 2;
    const int rowBase = blockIdx.y * 128, colBase = blockIdx.x * 64;

    const int rs  = t >> 3;
    const int c4  = (t & 7) << 2;

    const float* aptr[4];
    bool aval[4];
#pragma unroll
    for (int i = 0; i < 4; i++) {
        int grow = rowBase + rs + 32 * i;
        aval[i] = (grow < M);
        const float* s; int ro;
        if (grow < t1)      { s = A0; ro = grow; }
        else if (grow < t2) { s = A1; ro = grow - t1; }
        else                { s = A2; ro = grow - t2; }
        aptr[i] = s + (size_t)ro * K + c4;
    }
    const float* bptr[2];
#pragma unroll
    for (int i = 0; i < 2; i++)
        bptr[i] = W + (size_t)(colBase + rs + 32 * i) * K + c4;

    float acc[2][4][4];
#pragma unroll
    for (int mi = 0; mi < 2; mi++)
#pragma unroll
        for (int ni = 0; ni < 4; ni++)
#pragma unroll
            for (int j = 0; j < 4; j++) acc[mi][ni][j] = 0.f;

    float4 ar[4], br[2];
#pragma unroll
    for (int i = 0; i < 4; i++)
        ar[i] = aval[i] ? *(const float4*)(aptr[i]) : make_float4(0.f, 0.f, 0.f, 0.f);
#pragma unroll
    for (int i = 0; i < 2; i++)
        br[i] = *(const float4*)(bptr[i]);

    for (int k0 = 0; k0 < K; k0 += 32) {
#pragma unroll
        for (int i = 0; i < 4; i++) {
            int r = rs + 32 * i;
            As[r][c4 + 0] = f2tf(ar[i].x); As[r][c4 + 1] = f2tf(ar[i].y);
            As[r][c4 + 2] = f2tf(ar[i].z); As[r][c4 + 3] = f2tf(ar[i].w);
        }
#pragma unroll
        for (int i = 0; i < 2; i++) {
            int r = rs + 32 * i;
            Bs[r][c4 + 0] = f2tf(br[i].x); Bs[r][c4 + 1] = f2tf(br[i].y);
            Bs[r][c4 + 2] = f2tf(br[i].z); Bs[r][c4 + 3] = f2tf(br[i].w);
        }
        __syncthreads();

        if (k0 + 32 < K) {
#pragma unroll
            for (int i = 0; i < 4; i++)
                ar[i] = aval[i] ? *(const float4*)(aptr[i] + k0 + 32)
                                : make_float4(0.f, 0.f, 0.f, 0.f);
#pragma unroll
            for (int i = 0; i < 2; i++)
                br[i] = *(const float4*)(bptr[i] + k0 + 32);
        }

#pragma unroll
        for (int ks = 0; ks < 4; ks++) {
            unsigned af[2][4], bf[4][2];
#pragma unroll
            for (int mi = 0; mi < 2; mi++) {
                int r0 = wm * 32 + mi * 16 + g;
                int c0 = ks * 8 + tig;
                af[mi][0] = As[r0][c0];
                af[mi][1] = As[r0 + 8][c0];
                af[mi][2] = As[r0][c0 + 4];
                af[mi][3] = As[r0 + 8][c0 + 4];
            }
#pragma unroll
            for (int ni = 0; ni < 4; ni++) {
                int n0 = wn * 32 + ni * 8 + g;
                int kk = ks * 8 + tig;
                bf[ni][0] = Bs[n0][kk];
                bf[ni][1] = Bs[n0][kk + 4];
            }
#pragma unroll
            for (int mi = 0; mi < 2; mi++)
#pragma unroll
                for (int ni = 0; ni < 4; ni++)
                    mma8(acc[mi][ni], af[mi], bf[ni]);
        }
        __syncthreads();
    }

#pragma unroll
    for (int mi = 0; mi < 2; mi++) {
#pragma unroll
        for (int ni = 0; ni < 4; ni++) {
            int col = colBase + wn * 32 + ni * 8 + 2 * tig;
            float b0 = bias ? bias[col] : 0.f;
            float b1 = bias ? bias[col + 1] : 0.f;
#pragma unroll
            for (int half = 0; half < 2; half++) {
                int row = rowBase + wm * 32 + mi * 16 + g + half * 8;
                if (row >= M) continue;
                float v0 = acc[mi][ni][half * 2 + 0] + b0;
                float v1 = acc[mi][ni][half * 2 + 1] + b1;
                if (MODE == 0) {
                    out1[(size_t)row * N + col]     = v0;
                    out1[(size_t)row * N + col + 1] = v1;
                } else if (MODE == 1) {
                    if (col < Dc) {
                        out1[(size_t)row * Dc + col]     = v0;
                        out1[(size_t)row * Dc + col + 1] = v1;
                    } else {
                        out2[(size_t)row * Dc + col - Dc]     = v0;
                        out2[(size_t)row * Dc + col - Dc + 1] = v1;
                    }
                } else {
                    int q = row >> 4;
                    if (q < RUc) {
                        out1[(size_t)row * Dc + col]     = v0;
                        out1[(size_t)row * Dc + col + 1] = v1;
                    } else {
                        v0 = fminf(10.0f, fmaxf(-10.0f, v0));
                        v1 = fminf(10.0f, fmaxf(-10.0f, v1));
                        out2[(size_t)(row - RUc * Bc) * Dc + col]     = v0;
                        out2[(size_t)(row - RUc * Bc) * Dc + col + 1] = v1;
                    }
                }
            }
        }
    }
}

// ---------------- BD dense: 64x64 tile, 256 threads (2q x 4p warps) ---------
// Tiles whose entire jj-range is >= len[b] are never read downstream -> skip.
__global__ void __launch_bounds__(256, 3)
bd_dense(const float* __restrict__ pbv, const int* __restrict__ lengths) {
    __shared__ unsigned As[64][68];
    __shared__ unsigned Bs[64][68];

    const int t = threadIdx.x;
    const int warp = t >> 5, lane = t & 31;
    const int g = lane >> 2, tig = lane & 3;
    const int wm = warp & 1, wn = warp >> 1;
    const int n = blockIdx.z, b = n >> 3, h = n & 7;
    const int rowBase = blockIdx.y * 64;                      // u0
    const int colBase = 448 - rowBase + blockIdx.x * 64;      // p0 (>= 0)

    // dead-tile skip: tile covers jj in [64*px-63, 64*px+63]
    if (64 * (int)blockIdx.x - 63 >= lengths[b]) return;

#pragma unroll
    for (int i = 0; i < 4; i++) {
        int idx = t + i * 256;
        int r = idx >> 4, c4 = (idx & 15) << 2;
        int u = rowBase + r;
        float4 v = *(const float4*)(g_query + ((size_t)(Rc + u) * Bc + b) * Dc + h * HDc + c4);
        float4 p = *(const float4*)(pbv + h * HDc + c4);
        v.x += p.x; v.y += p.y; v.z += p.z; v.w += p.w;
        As[r][c4 + 0] = f2tf(v.x); As[r][c4 + 1] = f2tf(v.y);
        As[r][c4 + 2] = f2tf(v.z); As[r][c4 + 3] = f2tf(v.w);
    }
#pragma unroll
    for (int i = 0; i < 4; i++) {
        int idx = t + i * 256;
        int r = idx >> 4, c4 = (idx & 15) << 2;
        int pp = colBase + r;
        float4 w = make_float4(0.f, 0.f, 0.f, 0.f);
        if (pp < PEc)
            w = *(const float4*)(g_pos + (size_t)pp * Dc + h * HDc + c4);
        Bs[r][c4 + 0] = f2tf(w.x); Bs[r][c4 + 1] = f2tf(w.y);
        Bs[r][c4 + 2] = f2tf(w.z); Bs[r][c4 + 3] = f2tf(w.w);
    }
    __syncthreads();

    float acc[2][2][4];
#pragma unroll
    for (int mi = 0; mi < 2; mi++)
#pragma unroll
        for (int ni = 0; ni < 2; ni++)
#pragma unroll
            for (int j = 0; j < 4; j++) acc[mi][ni][j] = 0.f;

#pragma unroll
    for (int ks = 0; ks < 8; ks++) {
        unsigned af[2][4], bf[2][2];
#pragma unroll
        for (int mi = 0; mi < 2; mi++) {
            int r0 = wm * 32 + mi * 16 + g;
            int c0 = ks * 8 + tig;
            af[mi][0] = As[r0][c0];     af[mi][1] = As[r0 + 8][c0];
            af[mi][2] = As[r0][c0 + 4]; af[mi][3] = As[r0 + 8][c0 + 4];
        }
#pragma unroll
        for (int ni = 0; ni < 2; ni++) {
            int n0 = wn * 16 + ni * 8 + g;
            int kk = ks * 8 + tig;
            bf[ni][0] = Bs[n0][kk];
            bf[ni][1] = Bs[n0][kk + 4];
        }
#pragma unroll
        for (int mi = 0; mi < 2; mi++)
#pragma unroll
            for (int ni = 0; ni < 2; ni++)
                mma8(acc[mi][ni], af[mi], bf[ni]);
    }

#pragma unroll
    for (int mi = 0; mi < 2; mi++) {
#pragma unroll
        for (int half = 0; half < 2; half++) {
            int u = rowBase + wm * 32 + mi * 16 + g + half * 8;
#pragma unroll
            for (int ni = 0; ni < 2; ni++) {
#pragma unroll
                for (int jc = 0; jc < 2; jc++) {
                    int p = colBase + wn * 16 + ni * 8 + 2 * tig + jc;
                    if (p >= PEc) continue;
                    int jj = p + u - (Uc - 1);
                    if (jj >= 0 && jj < Uc)
                        g_bd[((size_t)n * Uc + u) * Uc + jj] = acc[mi][ni][half * 2 + jc];
                }
            }
        }
    }
}

// ---------------- fused attention: S = QK^T + bd, softmax, O = P V ----------
// Tiles with k0 >= cutoff are entirely masked (exact NEG_INF -> exp underflow
// to 0 given any unmasked entry earlier) -> loop only kt < ceil(cutoff/64).
__global__ void __launch_bounds__(128)
fused_attn(const float* __restrict__ keyt,
           const float* __restrict__ valt,
           const float* __restrict__ pbu,
           const unsigned* __restrict__ mask,
           const int* __restrict__ lengths) {
    extern __shared__ unsigned char dynsmem[];
    unsigned (*Qs)[68] = (unsigned (*)[68])(dynsmem);             // 17408B
    unsigned (*Ks)[68] = (unsigned (*)[68])(dynsmem + 17408);     // 17408B
    unsigned (*Vs)[72] = (unsigned (*)[72])(dynsmem + 34816);     // 18432B
    unsigned (*Ps)[68] = (unsigned (*)[68])(dynsmem + 53248);     // 17408B
    float    (*Ms)[68] = (float    (*)[68])(dynsmem + 53248);     // same region
    __shared__ float redm[2][64];
    __shared__ float reds[2][64];

    const int t = threadIdx.x;
    const int warp = t >> 5, lane = t & 31;
    const int g = lane >> 2, tig = lane & 3;
    const int wm = warp & 1, wn = warp >> 1;
    const int qBase = blockIdx.x * 64;
    const int n = blockIdx.y, b = n >> 3, h = n & 7;
    const int cutoff = (Mc + Rc) + lengths[b];
    const int ktEnd = (cutoff + 63) >> 6;     // tiles with k0 < cutoff

#pragma unroll
    for (int i = 0; i < 8; i++) {
        int idx = t + i * 128;
        int r = idx >> 4, c4 = (idx & 15) << 2;
        int q = qBase + r;
        float4 v = make_float4(0.f, 0.f, 0.f, 0.f);
        if (q < Qc) {
            v = *(const float4*)(g_query + ((size_t)q * Bc + b) * Dc + h * HDc + c4);
            float4 p = *(const float4*)(pbu + h * HDc + c4);
            v.x += p.x; v.y += p.y; v.z += p.z; v.w += p.w;
        }
        Qs[r][c4 + 0] = f2tf(v.x); Qs[r][c4 + 1] = f2tf(v.y);
        Qs[r][c4 + 2] = f2tf(v.z); Qs[r][c4 + 3] = f2tf(v.w);
    }

    float o[2][4][4];
#pragma unroll
    for (int mi = 0; mi < 2; mi++)
#pragma unroll
        for (int ni = 0; ni < 4; ni++)
#pragma unroll
            for (int j = 0; j < 4; j++) o[mi][ni][j] = 0.f;
    float mrun[2][2], lrun[2][2];
#pragma unroll
    for (int mi = 0; mi < 2; mi++)
#pragma unroll
        for (int hf = 0; hf < 2; hf++) { mrun[mi][hf] = -3.0e38f; lrun[mi][hf] = 0.f; }

    for (int kt = 0; kt < ktEnd; kt++) {
        const int k0 = kt * 64;
        const bool hasbd = (kt >= 1);
        __syncthreads();

#pragma unroll
        for (int i = 0; i < 8; i++) {
            int idx = t + i * 128;
            int r = idx >> 4, c4 = (idx & 15) << 2;
            size_t goff = ((size_t)(k0 + r) * Bc + b) * Dc + h * HDc + c4;
            float4 kv = *(const float4*)(keyt + goff);
            Ks[r][c4 + 0] = f2tf(kv.x); Ks[r][c4 + 1] = f2tf(kv.y);
            Ks[r][c4 + 2] = f2tf(kv.z); Ks[r][c4 + 3] = f2tf(kv.w);
            float4 vv = *(const float4*)(valt + goff);
            Vs[r][c4 + 0] = f2tf(vv.x); Vs[r][c4 + 1] = f2tf(vv.y);
            Vs[r][c4 + 2] = f2tf(vv.z); Vs[r][c4 + 3] = f2tf(vv.w);

            int q = qBase + r;
            int k = k0 + c4;
            float4 st;
            if (q < Qc) {
                uint4 mk = *(const uint4*)(mask + (size_t)q * KVc + k);
                float4 bd4 = make_float4(0.f, 0.f, 0.f, 0.f);
                if (hasbd && q >= Rc && q < Rc + Uc)
                    bd4 = *(const float4*)(g_bd + ((size_t)n * Uc + (q - Rc)) * Uc + (k - (Mc + Rc)));
                st.x = (mk.x != 0u || k + 0 >= cutoff) ? -1e30f : bd4.x;
                st.y = (mk.y != 0u || k + 1 >= cutoff) ? -1e30f : bd4.y;
                st.z = (mk.z != 0u || k + 2 >= cutoff) ? -1e30f : bd4.z;
                st.w = (mk.w != 0u || k + 3 >= cutoff) ? -1e30f : bd4.w;
            } else {
                st = make_float4(-1e30f, -1e30f, -1e30f, -1e30f);
            }
            *(float4*)&Ms[r][c4] = st;
        }
        __syncthreads();

        float s[2][4][4];
#pragma unroll
        for (int mi = 0; mi < 2; mi++)
#pragma unroll
            for (int ni = 0; ni < 4; ni++)
#pragma unroll
                for (int j = 0; j < 4; j++) s[mi][ni][j] = 0.f;
#pragma unroll
        for (int ks = 0; ks < 8; ks++) {
            unsigned af[2][4], bf[4][2];
#pragma unroll
            for (int mi = 0; mi < 2; mi++) {
                int r0 = wm * 32 + mi * 16 + g;
                int c0 = ks * 8 + tig;
                af[mi][0] = Qs[r0][c0];     af[mi][1] = Qs[r0 + 8][c0];
                af[mi][2] = Qs[r0][c0 + 4]; af[mi][3] = Qs[r0 + 8][c0 + 4];
            }
#pragma unroll
            for (int ni = 0; ni < 4; ni++) {
                int n0 = wn * 32 + ni * 8 + g;
                int kk = ks * 8 + tig;
                bf[ni][0] = Ks[n0][kk];
                bf[ni][1] = Ks[n0][kk + 4];
            }
#pragma unroll
            for (int mi = 0; mi < 2; mi++)
#pragma unroll
                for (int ni = 0; ni < 4; ni++)
                    mma8(s[mi][ni], af[mi], bf[ni]);
        }

#pragma unroll
        for (int mi = 0; mi < 2; mi++)
#pragma unroll
            for (int j = 0; j < 4; j++) {
                int row = wm * 32 + mi * 16 + (j >> 1) * 8 + g;
#pragma unroll
                for (int ni = 0; ni < 4; ni++) {
                    int col = wn * 32 + ni * 8 + 2 * tig + (j & 1);
                    float v = (s[mi][ni][j] + Ms[row][col]) * SCALE_F;
                    s[mi][ni][j] = fmaxf(v, NEG_INF_F);
                }
            }

#pragma unroll
        for (int mi = 0; mi < 2; mi++)
#pragma unroll
            for (int hf = 0; hf < 2; hf++) {
                float x = -3.4e38f;
#pragma unroll
                for (int ni = 0; ni < 4; ni++)
                    x = fmaxf(x, fmaxf(s[mi][ni][2 * hf], s[mi][ni][2 * hf + 1]));
                x = fmaxf(x, __shfl_xor_sync(0xffffffffu, x, 1));
                x = fmaxf(x, __shfl_xor_sync(0xffffffffu, x, 2));
                if (tig == 0) redm[wn][wm * 32 + mi * 16 + hf * 8 + g] = x;
            }
        __syncthreads();

        float mnew[2][2], fac[2][2];
#pragma unroll
        for (int mi = 0; mi < 2; mi++)
#pragma unroll
            for (int hf = 0; hf < 2; hf++) {
                int row = wm * 32 + mi * 16 + hf * 8 + g;
                float mt = fmaxf(redm[0][row], redm[1][row]);
                float mn = fmaxf(mrun[mi][hf], mt);
                fac[mi][hf] = __expf(mrun[mi][hf] - mn);
                mnew[mi][hf] = mn;
            }

#pragma unroll
        for (int mi = 0; mi < 2; mi++)
#pragma unroll
            for (int hf = 0; hf < 2; hf++) {
                float ssum = 0.f;
#pragma unroll
                for (int ni = 0; ni < 4; ni++) {
#pragma unroll
                    for (int c = 0; c < 2; c++) {
                        float p = __expf(s[mi][ni][2 * hf + c] - mnew[mi][hf]);
                        s[mi][ni][2 * hf + c] = p;
                        ssum += p;
                    }
                }
                ssum += __shfl_xor_sync(0xffffffffu, ssum, 1);
                ssum += __shfl_xor_sync(0xffffffffu, ssum, 2);
                if (tig == 0) reds[wn][wm * 32 + mi * 16 + hf * 8 + g] = ssum;
            }

#pragma unroll
        for (int mi = 0; mi < 2; mi++)
#pragma unroll
            for (int ni = 0; ni < 4; ni++)
#pragma unroll
                for (int j = 0; j < 4; j++)
                    o[mi][ni][j] *= fac[mi][j >> 1];

#pragma unroll
        for (int mi = 0; mi < 2; mi++)
#pragma unroll
            for (int j = 0; j < 4; j++) {
                int row = wm * 32 + mi * 16 + (j >> 1) * 8 + g;
#pragma unroll
                for (int ni = 0; ni < 4; ni++) {
                    int col = wn * 32 + ni * 8 + 2 * tig + (j & 1);
                    Ps[row][col] = f2tf(s[mi][ni][j]);
                }
            }
        __syncthreads();

#pragma unroll
        for (int mi = 0; mi < 2; mi++)
#pragma unroll
            for (int hf = 0; hf < 2; hf++) {
                int row = wm * 32 + mi * 16 + hf * 8 + g;
                lrun[mi][hf] = lrun[mi][hf] * fac[mi][hf] + reds[0][row] + reds[1][row];
                mrun[mi][hf] = mnew[mi][hf];
            }

#pragma unroll
        for (int ks = 0; ks < 8; ks++) {
            unsigned af[2][4], bf[4][2];
#pragma unroll
            for (int mi = 0; mi < 2; mi++) {
                int r0 = wm * 32 + mi * 16 + g;
                int c0 = ks * 8 + tig;
                af[mi][0] = Ps[r0][c0];     af[mi][1] = Ps[r0 + 8][c0];
                af[mi][2] = Ps[r0][c0 + 4]; af[mi][3] = Ps[r0 + 8][c0 + 4];
            }
#pragma unroll
            for (int ni = 0; ni < 4; ni++) {
                int col = wn * 32 + ni * 8 + g;
                int kk = ks * 8 + tig;
                bf[ni][0] = Vs[kk][col];
                bf[ni][1] = Vs[kk + 4][col];
            }
#pragma unroll
            for (int mi = 0; mi < 2; mi++)
#pragma unroll
                for (int ni = 0; ni < 4; ni++)
                    mma8(o[mi][ni], af[mi], bf[ni]);
        }
    }

#pragma unroll
    for (int mi = 0; mi < 2; mi++)
#pragma unroll
        for (int j = 0; j < 4; j++) {
            int row = wm * 32 + mi * 16 + (j >> 1) * 8 + g;
            int q = qBase + row;
            if (q >= Qc) continue;
            float inv = 1.0f / lrun[mi][j >> 1];
#pragma unroll
            for (int ni = 0; ni < 4; ni++) {
                int d = wn * 32 + ni * 8 + 2 * tig + (j & 1);
                g_attn[((size_t)q * Bc + b) * Dc + h * HDc + d] = o[mi][ni][j] * inv;
            }
        }
}

// ---------------- launch (fork-join concurrency on static streams) ----------
extern "C" void kernel_launch(void* const* d_in, const int* in_sizes, int n_in,
                              void* d_out, int out_size) {
    const float*    utterance     = (const float*)d_in[0];
    const int*      lengths       = (const int*)d_in[1];
    const float*    right_context = (const float*)d_in[2];
    const float*    summary       = (const float*)d_in[3];
    const float*    memory        = (const float*)d_in[4];
    const unsigned* attn_mask     = (const unsigned*)d_in[5];
    const float*    pos_emb       = (const float*)d_in[6];
    const float*    Wq            = (const float*)d_in[7];
    const float*    bq            = (const float*)d_in[8];
    const float*    Wkv           = (const float*)d_in[9];
    const float*    bkv           = (const float*)d_in[10];
    const float*    Wo            = (const float*)d_in[11];
    const float*    bo            = (const float*)d_in[12];
    const float*    Wpos          = (const float*)d_in[13];
    const float*    pbu           = (const float*)d_in[14];
    const float*    pbv           = (const float*)d_in[15];

    float* out      = (float*)d_out;
    float* out_rcu  = out;                                    // (R+U, B, D)
    float* out_mem  = out + (size_t)RUc * Bc * Dc;            // (S, B, D)
    float* out_key  = out + (size_t)Qc * Bc * Dc;             // (KV, B, D)
    float* out_val  = out_key + (size_t)KVc * Bc * Dc;        // (KV, B, D)

    void *p_query_, *p_pos_, *p_attn_;
    cudaGetSymbolAddress(&p_query_, g_query);
    cudaGetSymbolAddress(&p_pos_,  g_pos);
    cudaGetSymbolAddress(&p_attn_, g_attn);
    float* p_query = (float*)p_query_;
    float* p_pos   = (float*)p_pos_;
    float* p_attn  = (float*)p_attn_;

    const int FUSED_SMEM = 70656;
    cudaFuncSetAttribute(fused_attn, cudaFuncAttributeMaxDynamicSharedMemorySize, FUSED_SMEM);

    // one-time stream/event setup (first call is the uncaptured correctness run)
    static cudaStream_t sA = nullptr, sB = nullptr;
    static cudaEvent_t  evRoot = nullptr, evKV = nullptr, evPos = nullptr;
    if (sA == nullptr) {
        cudaStreamCreateWithFlags(&sA, cudaStreamNonBlocking);
        cudaStreamCreateWithFlags(&sB, cudaStreamNonBlocking);
        cudaEventCreateWithFlags(&evRoot, cudaEventDisableTiming);
        cudaEventCreateWithFlags(&evKV,  cudaEventDisableTiming);
        cudaEventCreateWithFlags(&evPos, cudaEventDisableTiming);
    }

    // fork: kv on sA, pos on sB, q on main stream — all independent
    cudaEventRecord(evRoot, 0);
    cudaStreamWaitEvent(sA, evRoot, 0);
    cudaStreamWaitEvent(sB, evRoot, 0);

    proj_mma<1><<<dim3((2 * Dc) / 64, (KVc * Bc) / 128), 256, 0, sA>>>(
        memory, right_context, utterance, Mc * Bc, (Mc + Rc) * Bc,
        Wkv, bkv, KVc * Bc, 2 * Dc, Dc, out_key, out_val);
    cudaEventRecord(evKV, sA);

    proj_mma<0><<<dim3(Dc / 64, (PEc + 127) / 128), 256, 0, sB>>>(
        pos_emb, pos_emb, pos_emb, PEc, PEc,
        Wpos, nullptr, PEc, Dc, Dc, p_pos, nullptr);
    cudaEventRecord(evPos, sB);

    proj_mma<0><<<dim3(Dc / 64, (Qc * Bc) / 128), 256>>>(
        right_context, utterance, summary, Rc * Bc, RUc * Bc,
        Wq, bq, Qc * Bc, Dc, Dc, p_query, nullptr);

    // bd needs q (in-order on main) + pos
    cudaStreamWaitEvent(0, evPos, 0);
    bd_dense<<<dim3(9, Uc / 64, BHc), 256>>>(pbv, lengths);

    // fused needs bd (in-order) + kv
    cudaStreamWaitEvent(0, evKV, 0);
    fused_attn<<<dim3((Qc + 63) / 64, BHc), 128, FUSED_SMEM>>>(out_key, out_val, pbu, attn_mask, lengths);

    // out-proj needs fused (in-order)
    proj_mma<2><<<dim3(Dc / 64, (Qc * Bc) / 128), 256>>>(
        p_attn, p_attn, p_attn, Qc * Bc, Qc * Bc,
        Wo, bo, Qc * Bc, Dc, Dc, out_rcu, out_mem);
}